// round 11
// baseline (speedup 1.0000x reference)
#include <cuda_runtime.h>

#define NN 100000
#define EE 500000
#define DD 128
#define RR 10
#define EPS 1e-5f

#define BUCK_SH 8
#define NBUCK ((NN + 255) >> BUCK_SH)          // 391
#define NBLK  200
#define CHUNK ((EE + NBLK - 1) / NBLK)         // 2500

// ---------------- scratch (device globals; no allocation allowed) ----------
__device__ float g_agg_in [NN * DD];
__device__ float g_agg_out[NN * DD];
__device__ float g_out    [NN * DD];
__device__ float g_x      [NN * DD];
__device__ float g_stats  [2][2 * DD];
__device__ float g_r1     [RR * DD];

// CSR build scratch (dir 0 = keyed by src -> agg_in ; dir 1 = keyed by dst)
__device__ int   g_bhist [2][NBLK][NBUCK];
__device__ int   g_bpos  [2][NBUCK][NBLK];
__device__ int   g_bstart[2][NBUCK + 1];
__device__ int   g_ebuf  [2][EE];    // (local<<21)|(type<<17)|nbr
__device__ int   g_off   [2][NN + 1];
__device__ float g_dinv  [2][NN];
__device__ int   g_nbr   [2][EE];    // (type<<17)|nbr

// ---------------- small helpers -------------------------------------------
__device__ __forceinline__ unsigned long long pk2(float lo, float hi) {
    unsigned long long r;
    asm("mov.b64 %0, {%1, %2};" : "=l"(r) : "f"(lo), "f"(hi));
    return r;
}
__device__ __forceinline__ void upk2(unsigned long long v, float& lo, float& hi) {
    asm("mov.b64 {%0, %1}, %2;" : "=f"(lo), "=f"(hi) : "l"(v));
}
__device__ __forceinline__ void fma2(unsigned long long& d,
                                     unsigned long long a, unsigned long long b) {
    asm("fma.rn.f32x2 %0, %1, %2, %0;" : "+l"(d) : "l"(a), "l"(b));
}
__device__ __forceinline__ float fast_tanh(float x) {
    float e = __expf(2.0f * x);
    return __fdividef(e - 1.0f, e + 1.0f);
}

// ---------------- misc zero -------------------------------------------------
__global__ void k_zero() {
    int i = threadIdx.x;
    if (i < 4 * DD) ((float*)g_stats)[i] = 0.f;
}

// ---------------- CSR build: bucket histogram (smem atomics only) -----------
__global__ __launch_bounds__(256)
void k_hist(const int* __restrict__ src, const int* __restrict__ dst) {
    int dir = blockIdx.y;
    const int* __restrict__ key = dir ? dst : src;
    __shared__ int bins[NBUCK];
    for (int i = threadIdx.x; i < NBUCK; i += blockDim.x) bins[i] = 0;
    __syncthreads();
    int beg = blockIdx.x * CHUNK;
    int end = min(beg + CHUNK, EE);
    for (int e = beg + threadIdx.x; e < end; e += blockDim.x)
        atomicAdd(&bins[key[e] >> BUCK_SH], 1);
    __syncthreads();
    for (int i = threadIdx.x; i < NBUCK; i += blockDim.x)
        g_bhist[dir][blockIdx.x][i] = bins[i];
}

// ---------------- CSR build: scan cursors (bucket-major x block) ------------
__global__ void k_bscan() {
    const int dir = blockIdx.x;
    const int M = NBUCK * NBLK;
    const int CH = (M + 1023) / 1024;
    int t = threadIdx.x;
    int base = t * CH;
    int s = 0;
    for (int i = 0; i < CH; i++) {
        int idx = base + i;
        if (idx < M) s += g_bhist[dir][idx % NBLK][idx / NBLK];
    }
    __shared__ int sm[1024];
    sm[t] = s;
    __syncthreads();
    for (int o = 1; o < 1024; o <<= 1) {
        int v = (t >= o) ? sm[t - o] : 0;
        __syncthreads();
        sm[t] += v;
        __syncthreads();
    }
    int run = sm[t] - s;   // exclusive prefix
    for (int i = 0; i < CH; i++) {
        int idx = base + i;
        if (idx < M) {
            int bu = idx / NBLK, bl = idx % NBLK;
            g_bpos[dir][bu][bl] = run;
            if (bl == 0) g_bstart[dir][bu] = run;
            run += g_bhist[dir][bl][bu];
        }
    }
    if (t == 1023) { g_bstart[dir][NBUCK] = EE; g_off[dir][NN] = EE; }
}

// ---------------- CSR build: scatter into buckets (smem cursors) ------------
__global__ __launch_bounds__(256)
void k_bscatter(const int* __restrict__ src, const int* __restrict__ dst,
                const int* __restrict__ typ) {
    int dir = blockIdx.y;
    const int* __restrict__ key = dir ? dst : src;
    const int* __restrict__ oth = dir ? src : dst;
    __shared__ int cur[NBUCK];
    int b = blockIdx.x;
    for (int i = threadIdx.x; i < NBUCK; i += blockDim.x)
        cur[i] = g_bpos[dir][i][b];
    __syncthreads();
    int beg = b * CHUNK;
    int end = min(beg + CHUNK, EE);
    for (int e = beg + threadIdx.x; e < end; e += blockDim.x) {
        int k = key[e];
        int pos = atomicAdd(&cur[k >> BUCK_SH], 1);
        g_ebuf[dir][pos] = ((k & 255) << 21) | (typ[e] << 17) | oth[e];
    }
}

// ---------------- CSR build: finalize per bucket (256 nodes) ----------------
__global__ __launch_bounds__(256)
void k_build() {
    int dir = blockIdx.y;
    int bu = blockIdx.x;
    int beg = g_bstart[dir][bu];
    int end = g_bstart[dir][bu + 1];
    int t = threadIdx.x;

    __shared__ int cnt[256];
    __shared__ int pre[256];
    cnt[t] = 0;
    __syncthreads();
    for (int p = beg + t; p < end; p += 256)
        atomicAdd(&cnt[g_ebuf[dir][p] >> 21], 1);
    __syncthreads();
    int v = cnt[t];
    pre[t] = v;
    __syncthreads();
    for (int o = 1; o < 256; o <<= 1) {
        int u = (t >= o) ? pre[t - o] : 0;
        __syncthreads();
        pre[t] += u;
        __syncthreads();
    }
    int excl = pre[t] - v;
    int node = (bu << BUCK_SH) + t;
    if (node < NN) {
        g_off[dir][node] = beg + excl;
        g_dinv[dir][node] = (v > 0) ? rsqrtf((float)v) : 0.0f;
    }
    cnt[t] = excl;      // reuse as cursor
    __syncthreads();
    for (int p = beg + t; p < end; p += 256) {
        int e = g_ebuf[dir][p];
        int pos = beg + atomicAdd(&cnt[e >> 21], 1);
        g_nbr[dir][pos] = e & 0x1FFFFF;
    }
}

// ---------------- gather aggregation: warp per (node, direction) ------------
__global__ __launch_bounds__(256)
void k_agg(const float* __restrict__ x, const float* __restrict__ r) {
    __shared__ float rs[RR * DD];
    for (int i = threadIdx.x; i < RR * DD; i += blockDim.x) rs[i] = r[i];
    __syncthreads();

    int gwarp = (blockIdx.x * blockDim.x + threadIdx.x) >> 5;
    int lane  = threadIdx.x & 31;
    if (gwarp >= 2 * NN) return;
    int dir = gwarp >= NN;
    int n   = gwarp - (dir ? NN : 0);

    const int*   __restrict__ off  = g_off[dir];
    const int*   __restrict__ nbr  = g_nbr[dir];
    const float* __restrict__ dinv = g_dinv[dir];
    float*       __restrict__ agg  = dir ? g_agg_out : g_agg_in;

    const float4* x4 = (const float4*)x;
    int beg = off[n], end = off[n + 1];

    float4 acc = make_float4(0.f, 0.f, 0.f, 0.f);
    int p = beg;
    for (; p + 4 <= end; p += 4) {
        int pk0 = nbr[p], pk1 = nbr[p + 1], pk2v = nbr[p + 2], pk3 = nbr[p + 3];
        int m0 = pk0 & 0x1FFFF, m1 = pk1 & 0x1FFFF;
        int m2 = pk2v & 0x1FFFF, m3 = pk3 & 0x1FFFF;
        float dv0 = dinv[m0], dv1 = dinv[m1], dv2 = dinv[m2], dv3 = dinv[m3];
        float4 xv0 = x4[m0 * 32 + lane];
        float4 xv1 = x4[m1 * 32 + lane];
        float4 xv2 = x4[m2 * 32 + lane];
        float4 xv3 = x4[m3 * 32 + lane];
        float4 rv0 = *(const float4*)&rs[(pk0 >> 17) * DD + lane * 4];
        float4 rv1 = *(const float4*)&rs[(pk1 >> 17) * DD + lane * 4];
        float4 rv2 = *(const float4*)&rs[(pk2v >> 17) * DD + lane * 4];
        float4 rv3 = *(const float4*)&rs[(pk3 >> 17) * DD + lane * 4];
        acc.x += dv0 * xv0.x * rv0.x + dv1 * xv1.x * rv1.x
               + dv2 * xv2.x * rv2.x + dv3 * xv3.x * rv3.x;
        acc.y += dv0 * xv0.y * rv0.y + dv1 * xv1.y * rv1.y
               + dv2 * xv2.y * rv2.y + dv3 * xv3.y * rv3.y;
        acc.z += dv0 * xv0.z * rv0.z + dv1 * xv1.z * rv1.z
               + dv2 * xv2.z * rv2.z + dv3 * xv3.z * rv3.z;
        acc.w += dv0 * xv0.w * rv0.w + dv1 * xv1.w * rv1.w
               + dv2 * xv2.w * rv2.w + dv3 * xv3.w * rv3.w;
    }
    for (; p < end; p++) {
        int pk = nbr[p];
        int m = pk & 0x1FFFF;
        float dv = dinv[m];
        float4 xv = x4[m * 32 + lane];
        float4 rv = *(const float4*)&rs[(pk >> 17) * DD + lane * 4];
        acc.x += dv * xv.x * rv.x;
        acc.y += dv * xv.y * rv.y;
        acc.z += dv * xv.z * rv.z;
        acc.w += dv * xv.w * rv.w;
    }
    float own = dinv[n];
    acc.x *= own; acc.y *= own; acc.z *= own; acc.w *= own;
    *(float4*)&agg[(size_t)n * DD + lane * 4] = acc;
}

// ---------------- fused 3-chunk GEMM + bias + BN partial stats --------------
__global__ __launch_bounds__(256)
void k_gemm(const float* __restrict__ x,
            const float* __restrict__ B0, const float* __restrict__ B1,
            const float* __restrict__ B2,
            const float* __restrict__ lr, const float* __restrict__ bias,
            int layer) {
    __shared__ float Ast[32][132];
    __shared__ float Bs [32][132];

    const int tid = threadIdx.x;
    const int tx = tid & 15;
    const int ty = tid >> 4;
    const int rowBase = blockIdx.x * 128;

    unsigned long long acc[8][4];
#pragma unroll
    for (int i = 0; i < 8; i++)
#pragma unroll
        for (int j = 0; j < 4; j++) acc[i][j] = 0ULL;

    for (int c = 0; c < 3; c++) {
        const float* A = (c == 0) ? g_agg_in : (c == 1) ? g_agg_out : x;
        const float* B = (c == 0) ? B0 : (c == 1) ? B1 : B2;
        for (int ks = 0; ks < 4; ks++) {
            __syncthreads();
            {
                int k4 = tid & 7;
                int r0 = tid >> 3;
#pragma unroll
                for (int rr = 0; rr < 4; rr++) {
                    int row = r0 + rr * 32;
                    int grow = rowBase + row;
                    float4 v = make_float4(0.f, 0.f, 0.f, 0.f);
                    if (grow < NN)
                        v = *(const float4*)&A[(size_t)grow * DD + ks * 32 + k4 * 4];
                    Ast[k4 * 4 + 0][row] = v.x;
                    Ast[k4 * 4 + 1][row] = v.y;
                    Ast[k4 * 4 + 2][row] = v.z;
                    Ast[k4 * 4 + 3][row] = v.w;
                }
            }
            {
                int c4 = tid & 31;
                int k0 = tid >> 5;
#pragma unroll
                for (int p = 0; p < 4; p++) {
                    int kk = k0 + p * 8;
                    int gk = ks * 32 + kk;
                    float4 v = *(const float4*)&B[gk * DD + c4 * 4];
                    if (c == 2) {
                        float sc = lr[gk];
                        v.x *= sc; v.y *= sc; v.z *= sc; v.w *= sc;
                    }
                    *(float4*)&Bs[kk][c4 * 4] = v;
                }
            }
            __syncthreads();
#pragma unroll 4
            for (int k = 0; k < 32; k++) {
                float4 a0 = *(const float4*)&Ast[k][ty * 8];
                float4 a1 = *(const float4*)&Ast[k][ty * 8 + 4];
                float4 b0 = *(const float4*)&Bs[k][tx * 8];
                float4 b1 = *(const float4*)&Bs[k][tx * 8 + 4];
                unsigned long long bp[4];
                bp[0] = pk2(b0.x, b0.y); bp[1] = pk2(b0.z, b0.w);
                bp[2] = pk2(b1.x, b1.y); bp[3] = pk2(b1.z, b1.w);
                float av[8] = {a0.x, a0.y, a0.z, a0.w, a1.x, a1.y, a1.z, a1.w};
#pragma unroll
                for (int i = 0; i < 8; i++) {
                    unsigned long long ap = pk2(av[i], av[i]);
#pragma unroll
                    for (int j = 0; j < 4; j++) fma2(acc[i][j], ap, bp[j]);
                }
            }
        }
    }

    const float third = 1.0f / 3.0f;
    float scol[8], qcol[8];
#pragma unroll
    for (int jj = 0; jj < 8; jj++) { scol[jj] = 0.f; qcol[jj] = 0.f; }
#pragma unroll
    for (int i = 0; i < 8; i++) {
        int grow = rowBase + ty * 8 + i;
        if (grow < NN) {
#pragma unroll
            for (int j = 0; j < 4; j++) {
                float lo, hi;
                upk2(acc[i][j], lo, hi);
                int col = tx * 8 + j * 2;
                lo = lo * third + bias[col];
                hi = hi * third + bias[col + 1];
                g_out[(size_t)grow * DD + col]     = lo;
                g_out[(size_t)grow * DD + col + 1] = hi;
                scol[j * 2]     += lo;  qcol[j * 2]     += lo * lo;
                scol[j * 2 + 1] += hi;  qcol[j * 2 + 1] += hi * hi;
            }
        }
    }

    __syncthreads();
    float* ssum = &Ast[0][0];
    float* ssq  = &Ast[0][0] + DD;
    if (tid < DD) { ssum[tid] = 0.f; ssq[tid] = 0.f; }
    __syncthreads();
#pragma unroll
    for (int jj = 0; jj < 8; jj++) {
        int col = tx * 8 + jj;
        atomicAdd(&ssum[col], scol[jj]);
        atomicAdd(&ssq[col], qcol[jj]);
    }
    __syncthreads();
    if (tid < DD) {
        atomicAdd(&g_stats[layer][tid], ssum[tid]);
        atomicAdd(&g_stats[layer][DD + tid], ssq[tid]);
    }
}

// ---------------- batchnorm normalize + fast tanh (float4) ------------------
__global__ __launch_bounds__(256)
void k_bn_tanh(float* __restrict__ xo, int layer) {
    int cg = threadIdx.x & 31;
    int rr = threadIdx.x >> 5;
    int c0 = cg * 4;
    float m0 = g_stats[layer][c0],     m1 = g_stats[layer][c0 + 1];
    float m2 = g_stats[layer][c0 + 2], m3 = g_stats[layer][c0 + 3];
    float q0 = g_stats[layer][DD + c0],     q1 = g_stats[layer][DD + c0 + 1];
    float q2 = g_stats[layer][DD + c0 + 2], q3 = g_stats[layer][DD + c0 + 3];
    const float invN = 1.0f / NN;
    m0 *= invN; m1 *= invN; m2 *= invN; m3 *= invN;
    float i0 = rsqrtf(q0 * invN - m0 * m0 + EPS);
    float i1 = rsqrtf(q1 * invN - m1 * m1 + EPS);
    float i2 = rsqrtf(q2 * invN - m2 * m2 + EPS);
    float i3 = rsqrtf(q3 * invN - m3 * m3 + EPS);
    for (int n = blockIdx.x * 8 + rr; n < NN; n += gridDim.x * 8) {
        float4 v = *(const float4*)&g_out[(size_t)n * DD + c0];
        v.x = fast_tanh((v.x - m0) * i0);
        v.y = fast_tanh((v.y - m1) * i1);
        v.z = fast_tanh((v.z - m2) * i2);
        v.w = fast_tanh((v.w - m3) * i3);
        *(float4*)&xo[(size_t)n * DD + c0] = v;
    }
}

// ---------------- relation transform r' = r @ W -----------------------------
__global__ void k_relmm(const float* __restrict__ r, const float* __restrict__ w,
                        float* __restrict__ ro) {
    int idx = blockIdx.x * blockDim.x + threadIdx.x;
    if (idx < RR * DD) {
        int i = idx / DD, j = idx % DD;
        float s = 0.f;
        for (int k = 0; k < DD; k++) s += r[i * DD + k] * w[k * DD + j];
        ro[idx] = s;
    }
}

// ---------------- launch ----------------------------------------------------
extern "C" void kernel_launch(void* const* d_in, const int* in_sizes, int n_in,
                              void* d_out, int out_size) {
    const float* x0       = (const float*)d_in[0];
    const float* r0       = (const float*)d_in[1];
    const float* w_in     = (const float*)d_in[2];
    const float* w_out    = (const float*)d_in[3];
    const float* w_loop   = (const float*)d_in[4];
    const float* w_rel    = (const float*)d_in[5];
    const float* loop_rel = (const float*)d_in[6];
    const float* bias     = (const float*)d_in[7];
    const int*   esrc     = (const int*)d_in[8];
    const int*   edst     = (const int*)d_in[9];
    const int*   etyp     = (const int*)d_in[10];

    float* out      = (float*)d_out;
    float* x_final  = out;
    float* r_final  = out + (size_t)NN * DD;

    const int GEMM_BLOCKS = (NN + 127) / 128;
    const int AGG_BLOCKS  = (2 * NN + 7) / 8;

    // CSR build — smem atomics only
    k_zero<<<1, 768>>>();
    k_hist<<<dim3(NBLK, 2), 256>>>(esrc, edst);
    k_bscan<<<2, 1024>>>();
    k_bscatter<<<dim3(NBLK, 2), 256>>>(esrc, edst, etyp);
    k_build<<<dim3(NBUCK, 2), 256>>>();

    // ---- layer 0 ----
    k_agg<<<AGG_BLOCKS, 256>>>(x0, r0);
    k_gemm<<<GEMM_BLOCKS, 256>>>(x0, w_in, w_out, w_loop, loop_rel, bias, 0);
    k_bn_tanh<<<512, 256>>>(g_x, 0);
    k_relmm<<<(RR * DD + 255) / 256, 256>>>(r0, w_rel, g_r1);

    // ---- layer 1 ----
    k_agg<<<AGG_BLOCKS, 256>>>(g_x, g_r1);
    k_gemm<<<GEMM_BLOCKS, 256>>>(g_x, w_in + DD * DD, w_out + DD * DD,
                                 w_loop + DD * DD, loop_rel + DD, bias + DD, 1);
    k_bn_tanh<<<512, 256>>>(x_final, 1);
    k_relmm<<<(RR * DD + 255) / 256, 256>>>(g_r1, w_rel + DD * DD, r_final);
}

// round 13
// speedup vs baseline: 1.0291x; 1.0291x over previous
#include <cuda_runtime.h>

#define NN 100000
#define EE 500000
#define DD 128
#define RR 10
#define EPS 1e-5f

#define BUCK_SH 8
#define NBUCK ((NN + 255) >> BUCK_SH)          // 391
#define NBLK  200
#define CHUNK ((EE + NBLK - 1) / NBLK)         // 2500

// ---------------- scratch (device globals; no allocation allowed) ----------
__device__ float g_agg_in [NN * DD];
__device__ float g_agg_out[NN * DD];
__device__ float g_out    [NN * DD];
__device__ float g_x      [NN * DD];
__device__ float g_stats  [2][2 * DD];
__device__ float g_r1     [RR * DD];

// CSR build scratch (dir 0 = keyed by src -> agg_in ; dir 1 = keyed by dst)
__device__ int   g_bhist [2][NBUCK][NBLK];   // [dir][bucket][block]
__device__ int   g_bpre  [2][NBUCK][NBLK];   // exclusive prefix within bucket
__device__ int   g_btot  [2][NBUCK];
__device__ int   g_bstart[2][NBUCK + 1];
__device__ int   g_ebuf  [2][EE];    // (local<<21)|(type<<17)|nbr
__device__ int   g_off   [2][NN + 1];
__device__ float g_dinv  [2][NN];
__device__ int   g_nbr   [2][EE];    // (type<<17)|nbr

// ---------------- small helpers -------------------------------------------
__device__ __forceinline__ unsigned long long pk2(float lo, float hi) {
    unsigned long long r;
    asm("mov.b64 %0, {%1, %2};" : "=l"(r) : "f"(lo), "f"(hi));
    return r;
}
__device__ __forceinline__ void upk2(unsigned long long v, float& lo, float& hi) {
    asm("mov.b64 {%0, %1}, %2;" : "=f"(lo), "=f"(hi) : "l"(v));
}
__device__ __forceinline__ void fma2(unsigned long long& d,
                                     unsigned long long a, unsigned long long b) {
    asm("fma.rn.f32x2 %0, %1, %2, %0;" : "+l"(d) : "l"(a), "l"(b));
}
__device__ __forceinline__ float fast_tanh(float x) {
    float e = __expf(2.0f * x);
    return __fdividef(e - 1.0f, e + 1.0f);
}

// ---------------- CSR build: bucket histogram (smem atomics only) -----------
__global__ __launch_bounds__(256)
void k_hist(const int* __restrict__ src, const int* __restrict__ dst) {
    int dir = blockIdx.y;
    const int* __restrict__ key = dir ? dst : src;
    __shared__ int bins[NBUCK];
    for (int i = threadIdx.x; i < NBUCK; i += blockDim.x) bins[i] = 0;
    __syncthreads();
    int beg = blockIdx.x * CHUNK;
    int end = min(beg + CHUNK, EE);
    for (int e = beg + threadIdx.x; e < end; e += blockDim.x)
        atomicAdd(&bins[key[e] >> BUCK_SH], 1);
    __syncthreads();
    for (int i = threadIdx.x; i < NBUCK; i += blockDim.x)
        g_bhist[dir][i][blockIdx.x] = bins[i];   // transposed: coalesced later
}

// ---------------- per-bucket scan over blocks (coalesced) -------------------
__global__ __launch_bounds__(256)
void k_btot() {
    int dir = blockIdx.y, bu = blockIdx.x;
    int t = threadIdx.x;
    __shared__ int sm[256];
    int v = (t < NBLK) ? g_bhist[dir][bu][t] : 0;
    sm[t] = v;
    __syncthreads();
    for (int o = 1; o < 256; o <<= 1) {
        int u = (t >= o) ? sm[t - o] : 0;
        __syncthreads();
        sm[t] += u;
        __syncthreads();
    }
    if (t < NBLK) g_bpre[dir][bu][t] = sm[t] - v;
    if (t == 255) g_btot[dir][bu] = sm[255];
}

// ---------------- top scan over buckets (one block) -------------------------
__global__ void k_btop() {
    int t = threadIdx.x;        // 1024
    int dir = t >> 9;
    int i = t & 511;
    __shared__ int sm[2][512];
    int v = (i < NBUCK) ? g_btot[dir][i] : 0;
    sm[dir][i] = v;
    __syncthreads();
    for (int o = 1; o < 512; o <<= 1) {
        int u = (i >= o) ? sm[dir][i - o] : 0;
        __syncthreads();
        sm[dir][i] += u;
        __syncthreads();
    }
    if (i <= NBUCK) g_bstart[dir][i] = sm[dir][i] - v;   // exclusive
    if (i == 0) g_off[dir][NN] = EE;
    if (t < 4 * DD) ((float*)g_stats)[t] = 0.f;          // zero BN stats
}

// ---------------- scatter into buckets (smem cursors) -----------------------
__global__ __launch_bounds__(256)
void k_bscatter(const int* __restrict__ src, const int* __restrict__ dst,
                const int* __restrict__ typ) {
    int dir = blockIdx.y;
    const int* __restrict__ key = dir ? dst : src;
    const int* __restrict__ oth = dir ? src : dst;
    __shared__ int cur[NBUCK];
    int b = blockIdx.x;
    for (int i = threadIdx.x; i < NBUCK; i += blockDim.x)
        cur[i] = g_bstart[dir][i] + g_bpre[dir][i][b];
    __syncthreads();
    int beg = b * CHUNK;
    int end = min(beg + CHUNK, EE);
    for (int e = beg + threadIdx.x; e < end; e += blockDim.x) {
        int k = key[e];
        int pos = atomicAdd(&cur[k >> BUCK_SH], 1);
        g_ebuf[dir][pos] = ((k & 255) << 21) | (typ[e] << 17) | oth[e];
    }
}

// ---------------- finalize per bucket (256 nodes) ---------------------------
__global__ __launch_bounds__(256)
void k_build() {
    int dir = blockIdx.y;
    int bu = blockIdx.x;
    int beg = g_bstart[dir][bu];
    int end = g_bstart[dir][bu + 1];
    int t = threadIdx.x;

    __shared__ int cnt[256];
    __shared__ int pre[256];
    cnt[t] = 0;
    __syncthreads();
    for (int p = beg + t; p < end; p += 256)
        atomicAdd(&cnt[g_ebuf[dir][p] >> 21], 1);
    __syncthreads();
    int v = cnt[t];
    pre[t] = v;
    __syncthreads();
    for (int o = 1; o < 256; o <<= 1) {
        int u = (t >= o) ? pre[t - o] : 0;
        __syncthreads();
        pre[t] += u;
        __syncthreads();
    }
    int excl = pre[t] - v;
    int node = (bu << BUCK_SH) + t;
    if (node < NN) {
        g_off[dir][node] = beg + excl;
        g_dinv[dir][node] = (v > 0) ? rsqrtf((float)v) : 0.0f;
    }
    cnt[t] = excl;
    __syncthreads();
    for (int p = beg + t; p < end; p += 256) {
        int e = g_ebuf[dir][p];
        int pos = beg + atomicAdd(&cnt[e >> 21], 1);
        g_nbr[dir][pos] = e & 0x1FFFFF;
    }
}

// ---------------- gather aggregation: warp per (node, direction) ------------
__global__ __launch_bounds__(256)
void k_agg(const float* __restrict__ x, const float* __restrict__ r) {
    __shared__ float rs[RR * DD];
    for (int i = threadIdx.x; i < RR * DD; i += blockDim.x) rs[i] = r[i];
    __syncthreads();

    int gwarp = (blockIdx.x * blockDim.x + threadIdx.x) >> 5;
    int lane  = threadIdx.x & 31;
    if (gwarp >= 2 * NN) return;
    int dir = gwarp >= NN;
    int n   = gwarp - (dir ? NN : 0);

    const int*   __restrict__ off  = g_off[dir];
    const int*   __restrict__ nbr  = g_nbr[dir];
    const float* __restrict__ dinv = g_dinv[dir];
    float*       __restrict__ agg  = dir ? g_agg_out : g_agg_in;

    const float4* x4 = (const float4*)x;
    int beg = off[n], end = off[n + 1];

    float4 acc = make_float4(0.f, 0.f, 0.f, 0.f);
    int p = beg;
    for (; p + 4 <= end; p += 4) {
        int pk0 = nbr[p], pk1 = nbr[p + 1], pk2v = nbr[p + 2], pk3 = nbr[p + 3];
        int m0 = pk0 & 0x1FFFF, m1 = pk1 & 0x1FFFF;
        int m2 = pk2v & 0x1FFFF, m3 = pk3 & 0x1FFFF;
        float dv0 = dinv[m0], dv1 = dinv[m1], dv2 = dinv[m2], dv3 = dinv[m3];
        float4 xv0 = x4[m0 * 32 + lane];
        float4 xv1 = x4[m1 * 32 + lane];
        float4 xv2 = x4[m2 * 32 + lane];
        float4 xv3 = x4[m3 * 32 + lane];
        float4 rv0 = *(const float4*)&rs[(pk0 >> 17) * DD + lane * 4];
        float4 rv1 = *(const float4*)&rs[(pk1 >> 17) * DD + lane * 4];
        float4 rv2 = *(const float4*)&rs[(pk2v >> 17) * DD + lane * 4];
        float4 rv3 = *(const float4*)&rs[(pk3 >> 17) * DD + lane * 4];
        acc.x += dv0 * xv0.x * rv0.x + dv1 * xv1.x * rv1.x
               + dv2 * xv2.x * rv2.x + dv3 * xv3.x * rv3.x;
        acc.y += dv0 * xv0.y * rv0.y + dv1 * xv1.y * rv1.y
               + dv2 * xv2.y * rv2.y + dv3 * xv3.y * rv3.y;
        acc.z += dv0 * xv0.z * rv0.z + dv1 * xv1.z * rv1.z
               + dv2 * xv2.z * rv2.z + dv3 * xv3.z * rv3.z;
        acc.w += dv0 * xv0.w * rv0.w + dv1 * xv1.w * rv1.w
               + dv2 * xv2.w * rv2.w + dv3 * xv3.w * rv3.w;
    }
    for (; p < end; p++) {
        int pk = nbr[p];
        int m = pk & 0x1FFFF;
        float dv = dinv[m];
        float4 xv = x4[m * 32 + lane];
        float4 rv = *(const float4*)&rs[(pk >> 17) * DD + lane * 4];
        acc.x += dv * xv.x * rv.x;
        acc.y += dv * xv.y * rv.y;
        acc.z += dv * xv.z * rv.z;
        acc.w += dv * xv.w * rv.w;
    }
    float own = dinv[n];
    acc.x *= own; acc.y *= own; acc.z *= own; acc.w *= own;
    *(float4*)&agg[(size_t)n * DD + lane * 4] = acc;
}

// ---------------- fused 3-chunk GEMM + bias + BN partial stats --------------
// A in smem as duplicated (a,a) u64 pairs [row][k]; B as interleaved pairs.
// Inner loop: 12 conflict-free LDS + 32 FFMA2, no packing movs.
__global__ __launch_bounds__(256)
void k_gemm(const float* __restrict__ x,
            const float* __restrict__ B0, const float* __restrict__ B1,
            const float* __restrict__ B2w,
            const float* __restrict__ lr, const float* __restrict__ bias,
            int layer) {
    __shared__ unsigned long long A2[128][32];  // [row][k] = (a,a)
    __shared__ unsigned long long B2[32][64];   // [k][(cp&3)*16 + (cp>>2)]

    const int tid = threadIdx.x;
    const int tx = tid & 15;
    const int ty = tid >> 4;
    const int rowBase = blockIdx.x * 128;

    unsigned long long acc[8][4];
#pragma unroll
    for (int i = 0; i < 8; i++)
#pragma unroll
        for (int j = 0; j < 4; j++) acc[i][j] = 0ULL;

    for (int c = 0; c < 3; c++) {
        const float* A = (c == 0) ? g_agg_in : (c == 1) ? g_agg_out : x;
        const float* B = (c == 0) ? B0 : (c == 1) ? B1 : B2w;
        for (int ks = 0; ks < 4; ks++) {
            __syncthreads();
            {   // A slice: 128 rows x 32 k, duplicated pairs, row-major
                int k4 = tid & 7;
                int r0 = tid >> 3;
#pragma unroll
                for (int rr = 0; rr < 4; rr++) {
                    int row = r0 + rr * 32;
                    int grow = rowBase + row;
                    float4 v = make_float4(0.f, 0.f, 0.f, 0.f);
                    if (grow < NN)
                        v = *(const float4*)&A[(size_t)grow * DD + ks * 32 + k4 * 4];
                    A2[row][k4 * 4 + 0] = pk2(v.x, v.x);
                    A2[row][k4 * 4 + 1] = pk2(v.y, v.y);
                    A2[row][k4 * 4 + 2] = pk2(v.z, v.z);
                    A2[row][k4 * 4 + 3] = pk2(v.w, v.w);
                }
            }
            {   // B slice: 32 k x 128 col as interleaved pairs
                int c4 = tid & 31;
                int k0 = tid >> 5;
#pragma unroll
                for (int p = 0; p < 4; p++) {
                    int kk = k0 + p * 8;
                    int gk = ks * 32 + kk;
                    float4 v = *(const float4*)&B[gk * DD + c4 * 4];
                    if (c == 2) {
                        float sc = lr[gk];
                        v.x *= sc; v.y *= sc; v.z *= sc; v.w *= sc;
                    }
                    int cp0 = c4 * 2;        // column-pair indices
                    int cp1 = c4 * 2 + 1;
                    B2[kk][(cp0 & 3) * 16 + (cp0 >> 2)] = pk2(v.x, v.y);
                    B2[kk][(cp1 & 3) * 16 + (cp1 >> 2)] = pk2(v.z, v.w);
                }
            }
            __syncthreads();
#pragma unroll 4
            for (int k = 0; k < 32; k++) {
                unsigned long long b0 = B2[k][0 * 16 + tx];
                unsigned long long b1 = B2[k][1 * 16 + tx];
                unsigned long long b2 = B2[k][2 * 16 + tx];
                unsigned long long b3 = B2[k][3 * 16 + tx];
#pragma unroll
                for (int i = 0; i < 8; i++) {
                    unsigned long long ai = A2[ty * 8 + i][k];
                    fma2(acc[i][0], ai, b0);
                    fma2(acc[i][1], ai, b1);
                    fma2(acc[i][2], ai, b2);
                    fma2(acc[i][3], ai, b3);
                }
            }
        }
    }

    // epilogue: scale + bias + store + BN partial stats
    // NOTE column mapping: acc[i][j] holds cols via cp = tx*4 + j -> cols 2cp, 2cp+1
    const float third = 1.0f / 3.0f;
    float scol[8], qcol[8];
#pragma unroll
    for (int jj = 0; jj < 8; jj++) { scol[jj] = 0.f; qcol[jj] = 0.f; }
#pragma unroll
    for (int i = 0; i < 8; i++) {
        int grow = rowBase + ty * 8 + i;
        if (grow < NN) {
#pragma unroll
            for (int j = 0; j < 4; j++) {
                float lo, hi;
                upk2(acc[i][j], lo, hi);
                int col = (tx * 4 + j) * 2;
                lo = lo * third + bias[col];
                hi = hi * third + bias[col + 1];
                g_out[(size_t)grow * DD + col]     = lo;
                g_out[(size_t)grow * DD + col + 1] = hi;
                scol[j * 2]     += lo;  qcol[j * 2]     += lo * lo;
                scol[j * 2 + 1] += hi;  qcol[j * 2 + 1] += hi * hi;
            }
        }
    }

    __syncthreads();
    float* ssum = (float*)&A2[0][0];
    float* ssq  = ssum + DD;
    if (tid < DD) { ssum[tid] = 0.f; ssq[tid] = 0.f; }
    __syncthreads();
#pragma unroll
    for (int jj = 0; jj < 8; jj++) {
        int col = tx * 8 + jj;           // cols (tx*4+j)*2 and +1 == tx*8 + jj
        atomicAdd(&ssum[col], scol[jj]);
        atomicAdd(&ssq[col], qcol[jj]);
    }
    __syncthreads();
    if (tid < DD) {
        atomicAdd(&g_stats[layer][tid], ssum[tid]);
        atomicAdd(&g_stats[layer][DD + tid], ssq[tid]);
    }
}

// ---------------- batchnorm normalize + fast tanh (float4) ------------------
__global__ __launch_bounds__(256)
void k_bn_tanh(float* __restrict__ xo, int layer) {
    int cg = threadIdx.x & 31;
    int rr = threadIdx.x >> 5;
    int c0 = cg * 4;
    float m0 = g_stats[layer][c0],     m1 = g_stats[layer][c0 + 1];
    float m2 = g_stats[layer][c0 + 2], m3 = g_stats[layer][c0 + 3];
    float q0 = g_stats[layer][DD + c0],     q1 = g_stats[layer][DD + c0 + 1];
    float q2 = g_stats[layer][DD + c0 + 2], q3 = g_stats[layer][DD + c0 + 3];
    const float invN = 1.0f / NN;
    m0 *= invN; m1 *= invN; m2 *= invN; m3 *= invN;
    float i0 = rsqrtf(q0 * invN - m0 * m0 + EPS);
    float i1 = rsqrtf(q1 * invN - m1 * m1 + EPS);
    float i2 = rsqrtf(q2 * invN - m2 * m2 + EPS);
    float i3 = rsqrtf(q3 * invN - m3 * m3 + EPS);
    for (int n = blockIdx.x * 8 + rr; n < NN; n += gridDim.x * 8) {
        float4 v = *(const float4*)&g_out[(size_t)n * DD + c0];
        v.x = fast_tanh((v.x - m0) * i0);
        v.y = fast_tanh((v.y - m1) * i1);
        v.z = fast_tanh((v.z - m2) * i2);
        v.w = fast_tanh((v.w - m3) * i3);
        *(float4*)&xo[(size_t)n * DD + c0] = v;
    }
}

// ---------------- relation transform r' = r @ W -----------------------------
__global__ void k_relmm(const float* __restrict__ r, const float* __restrict__ w,
                        float* __restrict__ ro) {
    int idx = blockIdx.x * blockDim.x + threadIdx.x;
    if (idx < RR * DD) {
        int i = idx / DD, j = idx % DD;
        float s = 0.f;
        for (int k = 0; k < DD; k++) s += r[i * DD + k] * w[k * DD + j];
        ro[idx] = s;
    }
}

// ---------------- launch ----------------------------------------------------
extern "C" void kernel_launch(void* const* d_in, const int* in_sizes, int n_in,
                              void* d_out, int out_size) {
    const float* x0       = (const float*)d_in[0];
    const float* r0       = (const float*)d_in[1];
    const float* w_in     = (const float*)d_in[2];
    const float* w_out    = (const float*)d_in[3];
    const float* w_loop   = (const float*)d_in[4];
    const float* w_rel    = (const float*)d_in[5];
    const float* loop_rel = (const float*)d_in[6];
    const float* bias     = (const float*)d_in[7];
    const int*   esrc     = (const int*)d_in[8];
    const int*   edst     = (const int*)d_in[9];
    const int*   etyp     = (const int*)d_in[10];

    float* out      = (float*)d_out;
    float* x_final  = out;
    float* r_final  = out + (size_t)NN * DD;

    const int GEMM_BLOCKS = (NN + 127) / 128;
    const int AGG_BLOCKS  = (2 * NN + 7) / 8;

    // CSR build — all-parallel, smem atomics only
    k_hist<<<dim3(NBLK, 2), 256>>>(esrc, edst);
    k_btot<<<dim3(NBUCK, 2), 256>>>();
    k_btop<<<1, 1024>>>();
    k_bscatter<<<dim3(NBLK, 2), 256>>>(esrc, edst, etyp);
    k_build<<<dim3(NBUCK, 2), 256>>>();

    // ---- layer 0 ----
    k_agg<<<AGG_BLOCKS, 256>>>(x0, r0);
    k_gemm<<<GEMM_BLOCKS, 256>>>(x0, w_in, w_out, w_loop, loop_rel, bias, 0);
    k_bn_tanh<<<512, 256>>>(g_x, 0);
    k_relmm<<<(RR * DD + 255) / 256, 256>>>(r0, w_rel, g_r1);

    // ---- layer 1 ----
    k_agg<<<AGG_BLOCKS, 256>>>(g_x, g_r1);
    k_gemm<<<GEMM_BLOCKS, 256>>>(g_x, w_in + DD * DD, w_out + DD * DD,
                                 w_loop + DD * DD, loop_rel + DD, bias + DD, 1);
    k_bn_tanh<<<512, 256>>>(x_final, 1);
    k_relmm<<<(RR * DD + 255) / 256, 256>>>(g_r1, w_rel + DD * DD, r_final);
}

// round 14
// speedup vs baseline: 2.5467x; 2.4747x over previous
#include <cuda_runtime.h>

#define NN 100000
#define EE 500000
#define DD 128
#define RR 10
#define EPS 1e-5f

#define BUCK_SH 8
#define NBUCK ((NN + 255) >> BUCK_SH)          // 391
#define NBLK  200
#define CHUNK ((EE + NBLK - 1) / NBLK)         // 2500
#define GEMM_TILES ((NN + 127) / 128)          // 782

typedef unsigned long long u64;

// ---------------- scratch (device globals; no allocation allowed) ----------
__device__ float g_agg_in [NN * DD];
__device__ float g_agg_out[NN * DD];
__device__ float g_out    [NN * DD];
__device__ float g_x      [NN * DD];
__device__ float g_stats  [2][2 * DD];
__device__ float g_r1     [RR * DD];

__device__ int   g_bhist [2][NBUCK][NBLK];
__device__ int   g_bpre  [2][NBUCK][NBLK];
__device__ int   g_btot  [2][NBUCK];
__device__ int   g_bstart[2][NBUCK + 1];
__device__ int   g_ebuf  [2][EE];    // (local<<21)|(type<<17)|nbr
__device__ int   g_off   [2][NN + 1];
__device__ float g_dinv  [2][NN];
__device__ int   g_nbr   [2][EE];    // (type<<17)|nbr

__device__ unsigned g_barc = 0;
__device__ unsigned g_barg = 0;

// ---------------- helpers ---------------------------------------------------
__device__ __forceinline__ u64 pk2(float lo, float hi) {
    u64 r; asm("mov.b64 %0, {%1, %2};" : "=l"(r) : "f"(lo), "f"(hi)); return r;
}
__device__ __forceinline__ void upk2(u64 v, float& lo, float& hi) {
    asm("mov.b64 {%0, %1}, %2;" : "=f"(lo), "=f"(hi) : "l"(v));
}
__device__ __forceinline__ void fma2(u64& d, u64 a, u64 b) {
    asm("fma.rn.f32x2 %0, %1, %2, %0;" : "+l"(d) : "l"(a), "l"(b));
}
__device__ __forceinline__ float fast_tanh(float x) {
    float e = __expf(2.0f * x);
    return __fdividef(e - 1.0f, e + 1.0f);
}

// grid-wide barrier: all blocks resident (grid sized by occupancy API)
__device__ __forceinline__ void gbar() {
    __syncthreads();
    if (threadIdx.x == 0) {
        __threadfence();
        unsigned gen = atomicAdd(&g_barg, 0u);
        if (atomicAdd(&g_barc, 1u) == gridDim.x - 1u) {
            atomicExch(&g_barc, 0u);
            __threadfence();
            atomicAdd(&g_barg, 1u);
        } else {
            while (atomicAdd(&g_barg, 0u) == gen) __nanosleep(200);
        }
        __threadfence();
    }
    __syncthreads();
}

// ---------------- the whole pipeline in one kernel --------------------------
__global__ __launch_bounds__(256, 2)
void k_fused(const float* __restrict__ x0, const float* __restrict__ r0,
             const float* __restrict__ w_in, const float* __restrict__ w_out,
             const float* __restrict__ w_loop, const float* __restrict__ w_rel,
             const float* __restrict__ loop_rel, const float* __restrict__ bias,
             const int* __restrict__ esrc, const int* __restrict__ edst,
             const int* __restrict__ etyp,
             float* __restrict__ x_final, float* __restrict__ r_final) {
    __shared__ __align__(16) unsigned char SU[49152];   // 48 KB union
    const int tid = threadIdx.x;
    const int NB = gridDim.x;

    // ===== Phase 0: bucket histograms + zero stats ==========================
    {
        int* bins = (int*)SU;
        if (blockIdx.x == 0)
            for (int i = tid; i < 4 * DD; i += 256) ((float*)g_stats)[i] = 0.f;
        for (int vb = blockIdx.x; vb < 2 * NBLK; vb += NB) {
            int dir = vb / NBLK, b = vb % NBLK;
            const int* __restrict__ key = dir ? edst : esrc;
            __syncthreads();
            for (int i = tid; i < NBUCK; i += 256) bins[i] = 0;
            __syncthreads();
            int beg = b * CHUNK, end = min(beg + CHUNK, EE);
            for (int e = beg + tid; e < end; e += 256)
                atomicAdd(&bins[key[e] >> BUCK_SH], 1);
            __syncthreads();
            for (int i = tid; i < NBUCK; i += 256)
                g_bhist[dir][i][b] = bins[i];
        }
    }
    gbar();

    // ===== Phase 1: per-bucket scan over blocks =============================
    {
        int* sm = (int*)SU;
        for (int vb = blockIdx.x; vb < 2 * NBUCK; vb += NB) {
            int dir = vb / NBUCK, bu = vb % NBUCK;
            __syncthreads();
            int v = (tid < NBLK) ? g_bhist[dir][bu][tid] : 0;
            sm[tid] = v;
            __syncthreads();
            for (int o = 1; o < 256; o <<= 1) {
                int u = (tid >= o) ? sm[tid - o] : 0;
                __syncthreads();
                sm[tid] += u;
                __syncthreads();
            }
            if (tid < NBLK) g_bpre[dir][bu][tid] = sm[tid] - v;
            if (tid == 255) g_btot[dir][bu] = sm[255];
        }
    }
    gbar();

    // ===== Phase 2: top scan over buckets (block 0) =========================
    if (blockIdx.x == 0) {
        int* sm = (int*)SU;
        for (int dir = 0; dir < 2; dir++) {
            int e0 = 2 * tid, e1 = 2 * tid + 1;
            int v0 = (e0 < NBUCK) ? g_btot[dir][e0] : 0;
            int v1 = (e1 < NBUCK) ? g_btot[dir][e1] : 0;
            int p = v0 + v1;
            __syncthreads();
            sm[tid] = p;
            __syncthreads();
            for (int o = 1; o < 256; o <<= 1) {
                int u = (tid >= o) ? sm[tid - o] : 0;
                __syncthreads();
                sm[tid] += u;
                __syncthreads();
            }
            int excl = sm[tid] - p;
            if (e0 < NBUCK) g_bstart[dir][e0] = excl;
            if (e1 < NBUCK) g_bstart[dir][e1] = excl + v0;
        }
        if (tid == 0) {
            g_bstart[0][NBUCK] = EE; g_bstart[1][NBUCK] = EE;
            g_off[0][NN] = EE; g_off[1][NN] = EE;
        }
    }
    gbar();

    // ===== Phase 3: scatter into buckets ====================================
    {
        int* cur = (int*)SU;
        for (int vb = blockIdx.x; vb < 2 * NBLK; vb += NB) {
            int dir = vb / NBLK, b = vb % NBLK;
            const int* __restrict__ key = dir ? edst : esrc;
            const int* __restrict__ oth = dir ? esrc : edst;
            __syncthreads();
            for (int i = tid; i < NBUCK; i += 256)
                cur[i] = g_bstart[dir][i] + g_bpre[dir][i][b];
            __syncthreads();
            int beg = b * CHUNK, end = min(beg + CHUNK, EE);
            for (int e = beg + tid; e < end; e += 256) {
                int k = key[e];
                int pos = atomicAdd(&cur[k >> BUCK_SH], 1);
                g_ebuf[dir][pos] = ((k & 255) << 21) | (etyp[e] << 17) | oth[e];
            }
        }
    }
    gbar();

    // ===== Phase 4: finalize CSR per bucket =================================
    {
        int* cnt = (int*)SU;
        int* pre = cnt + 256;
        for (int vb = blockIdx.x; vb < 2 * NBUCK; vb += NB) {
            int dir = vb / NBUCK, bu = vb % NBUCK;
            int beg = g_bstart[dir][bu], end = g_bstart[dir][bu + 1];
            __syncthreads();
            cnt[tid] = 0;
            __syncthreads();
            for (int p = beg + tid; p < end; p += 256)
                atomicAdd(&cnt[g_ebuf[dir][p] >> 21], 1);
            __syncthreads();
            int v = cnt[tid];
            pre[tid] = v;
            __syncthreads();
            for (int o = 1; o < 256; o <<= 1) {
                int u = (tid >= o) ? pre[tid - o] : 0;
                __syncthreads();
                pre[tid] += u;
                __syncthreads();
            }
            int excl = pre[tid] - v;
            int node = (bu << BUCK_SH) + tid;
            if (node < NN) {
                g_off[dir][node] = beg + excl;
                g_dinv[dir][node] = (v > 0) ? rsqrtf((float)v) : 0.0f;
            }
            __syncthreads();
            cnt[tid] = excl;
            __syncthreads();
            for (int p = beg + tid; p < end; p += 256) {
                int e = g_ebuf[dir][p];
                int pos = beg + atomicAdd(&cnt[e >> 21], 1);
                g_nbr[dir][pos] = e & 0x1FFFFF;
            }
        }
    }
    gbar();

    // ===== Layers ===========================================================
    for (int l = 0; l < 2; l++) {
        const float* xin = l ? g_x : x0;
        const float* rin = l ? g_r1 : r0;
        const float* B0 = w_in  + l * DD * DD;
        const float* B1 = w_out + l * DD * DD;
        const float* B2w = w_loop + l * DD * DD;
        const float* lr = loop_rel + l * DD;
        const float* bi = bias + l * DD;
        float* xout = l ? x_final : g_x;
        float* rout = l ? r_final : g_r1;

        // ---- aggregation (warp per (node,dir)) ----
        {
            float* rs = (float*)SU;
            for (int i = tid; i < RR * DD; i += 256) rs[i] = rin[i];
            __syncthreads();
            int wid = tid >> 5, lane = tid & 31;
            const float4* x4 = (const float4*)xin;
            for (int pr = blockIdx.x * 8 + wid; pr < 2 * NN; pr += NB * 8) {
                int dir = pr >= NN;
                int n = pr - (dir ? NN : 0);
                const int* __restrict__ off = g_off[dir];
                const int* __restrict__ nbr = g_nbr[dir];
                const float* __restrict__ dinv = g_dinv[dir];
                float* __restrict__ agg = dir ? g_agg_out : g_agg_in;
                int beg = off[n], end = off[n + 1];
                float4 acc = make_float4(0.f, 0.f, 0.f, 0.f);
                int p = beg;
                for (; p + 4 <= end; p += 4) {
                    int pk0 = nbr[p], pk1 = nbr[p + 1];
                    int pk2v = nbr[p + 2], pk3 = nbr[p + 3];
                    int m0 = pk0 & 0x1FFFF, m1 = pk1 & 0x1FFFF;
                    int m2 = pk2v & 0x1FFFF, m3 = pk3 & 0x1FFFF;
                    float dv0 = dinv[m0], dv1 = dinv[m1];
                    float dv2 = dinv[m2], dv3 = dinv[m3];
                    float4 xv0 = x4[m0 * 32 + lane];
                    float4 xv1 = x4[m1 * 32 + lane];
                    float4 xv2 = x4[m2 * 32 + lane];
                    float4 xv3 = x4[m3 * 32 + lane];
                    float4 rv0 = *(const float4*)&rs[(pk0 >> 17) * DD + lane * 4];
                    float4 rv1 = *(const float4*)&rs[(pk1 >> 17) * DD + lane * 4];
                    float4 rv2 = *(const float4*)&rs[(pk2v >> 17) * DD + lane * 4];
                    float4 rv3 = *(const float4*)&rs[(pk3 >> 17) * DD + lane * 4];
                    acc.x += dv0 * xv0.x * rv0.x + dv1 * xv1.x * rv1.x
                           + dv2 * xv2.x * rv2.x + dv3 * xv3.x * rv3.x;
                    acc.y += dv0 * xv0.y * rv0.y + dv1 * xv1.y * rv1.y
                           + dv2 * xv2.y * rv2.y + dv3 * xv3.y * rv3.y;
                    acc.z += dv0 * xv0.z * rv0.z + dv1 * xv1.z * rv1.z
                           + dv2 * xv2.z * rv2.z + dv3 * xv3.z * rv3.z;
                    acc.w += dv0 * xv0.w * rv0.w + dv1 * xv1.w * rv1.w
                           + dv2 * xv2.w * rv2.w + dv3 * xv3.w * rv3.w;
                }
                for (; p < end; p++) {
                    int pk = nbr[p];
                    int m = pk & 0x1FFFF;
                    float dv = dinv[m];
                    float4 xv = x4[m * 32 + lane];
                    float4 rv = *(const float4*)&rs[(pk >> 17) * DD + lane * 4];
                    acc.x += dv * xv.x * rv.x;
                    acc.y += dv * xv.y * rv.y;
                    acc.z += dv * xv.z * rv.z;
                    acc.w += dv * xv.w * rv.w;
                }
                float own = dinv[n];
                acc.x *= own; acc.y *= own; acc.z *= own; acc.w *= own;
                *(float4*)&agg[(size_t)n * DD + lane * 4] = acc;
            }
        }
        gbar();

        // ---- GEMM + bias + BN partial stats ----
        {
            u64 (*A2)[32] = (u64(*)[32])SU;            // 32 KB
            u64 (*B2)[64] = (u64(*)[64])(SU + 32768);  // 16 KB
            const int tx = tid & 15;
            const int ty = tid >> 4;
            for (int tile = blockIdx.x; tile < GEMM_TILES; tile += NB) {
                const int rowBase = tile * 128;
                u64 acc[8][4];
#pragma unroll
                for (int i = 0; i < 8; i++)
#pragma unroll
                    for (int j = 0; j < 4; j++) acc[i][j] = 0ULL;

                for (int c = 0; c < 3; c++) {
                    const float* A = (c == 0) ? g_agg_in : (c == 1) ? g_agg_out : xin;
                    const float* B = (c == 0) ? B0 : (c == 1) ? B1 : B2w;
                    for (int ks = 0; ks < 4; ks++) {
                        __syncthreads();
                        {
                            int k4 = tid & 7;
                            int r0i = tid >> 3;
#pragma unroll
                            for (int rr = 0; rr < 4; rr++) {
                                int row = r0i + rr * 32;
                                int grow = rowBase + row;
                                float4 v = make_float4(0.f, 0.f, 0.f, 0.f);
                                if (grow < NN)
                                    v = *(const float4*)&A[(size_t)grow * DD + ks * 32 + k4 * 4];
                                A2[row][k4 * 4 + 0] = pk2(v.x, v.x);
                                A2[row][k4 * 4 + 1] = pk2(v.y, v.y);
                                A2[row][k4 * 4 + 2] = pk2(v.z, v.z);
                                A2[row][k4 * 4 + 3] = pk2(v.w, v.w);
                            }
                        }
                        {
                            int c4 = tid & 31;
                            int k0 = tid >> 5;
#pragma unroll
                            for (int p = 0; p < 4; p++) {
                                int kk = k0 + p * 8;
                                int gk = ks * 32 + kk;
                                float4 v = *(const float4*)&B[gk * DD + c4 * 4];
                                if (c == 2) {
                                    float sc = lr[gk];
                                    v.x *= sc; v.y *= sc; v.z *= sc; v.w *= sc;
                                }
                                int cp0 = c4 * 2, cp1 = c4 * 2 + 1;
                                B2[kk][(cp0 & 3) * 16 + (cp0 >> 2)] = pk2(v.x, v.y);
                                B2[kk][(cp1 & 3) * 16 + (cp1 >> 2)] = pk2(v.z, v.w);
                            }
                        }
                        __syncthreads();
#pragma unroll 4
                        for (int k = 0; k < 32; k++) {
                            u64 b0 = B2[k][0 * 16 + tx];
                            u64 b1 = B2[k][1 * 16 + tx];
                            u64 b2 = B2[k][2 * 16 + tx];
                            u64 b3 = B2[k][3 * 16 + tx];
#pragma unroll
                            for (int i = 0; i < 8; i++) {
                                u64 ai = A2[ty * 8 + i][k];
                                fma2(acc[i][0], ai, b0);
                                fma2(acc[i][1], ai, b1);
                                fma2(acc[i][2], ai, b2);
                                fma2(acc[i][3], ai, b3);
                            }
                        }
                    }
                }

                const float third = 1.0f / 3.0f;
                float scol[8], qcol[8];
#pragma unroll
                for (int jj = 0; jj < 8; jj++) { scol[jj] = 0.f; qcol[jj] = 0.f; }
#pragma unroll
                for (int i = 0; i < 8; i++) {
                    int grow = rowBase + ty * 8 + i;
                    if (grow < NN) {
#pragma unroll
                        for (int j = 0; j < 4; j++) {
                            float lo, hi;
                            upk2(acc[i][j], lo, hi);
                            int col = (tx * 4 + j) * 2;
                            lo = lo * third + bi[col];
                            hi = hi * third + bi[col + 1];
                            g_out[(size_t)grow * DD + col]     = lo;
                            g_out[(size_t)grow * DD + col + 1] = hi;
                            scol[j * 2]     += lo;  qcol[j * 2]     += lo * lo;
                            scol[j * 2 + 1] += hi;  qcol[j * 2 + 1] += hi * hi;
                        }
                    }
                }

                __syncthreads();
                float* ssum = (float*)SU;
                float* ssq  = ssum + DD;
                if (tid < DD) { ssum[tid] = 0.f; ssq[tid] = 0.f; }
                __syncthreads();
#pragma unroll
                for (int jj = 0; jj < 8; jj++) {
                    int col = tx * 8 + jj;
                    atomicAdd(&ssum[col], scol[jj]);
                    atomicAdd(&ssq[col], qcol[jj]);
                }
                __syncthreads();
                if (tid < DD) {
                    atomicAdd(&g_stats[l][tid], ssum[tid]);
                    atomicAdd(&g_stats[l][DD + tid], ssq[tid]);
                }
                __syncthreads();
            }
        }
        gbar();

        // ---- BN normalize + tanh, and relation transform ----
        {
            int cg = tid & 31;
            int rr = tid >> 5;
            int c0 = cg * 4;
            const float invN = 1.0f / NN;
            float m0 = g_stats[l][c0] * invN,     m1 = g_stats[l][c0 + 1] * invN;
            float m2 = g_stats[l][c0 + 2] * invN, m3 = g_stats[l][c0 + 3] * invN;
            float i0 = rsqrtf(g_stats[l][DD + c0] * invN - m0 * m0 + EPS);
            float i1 = rsqrtf(g_stats[l][DD + c0 + 1] * invN - m1 * m1 + EPS);
            float i2 = rsqrtf(g_stats[l][DD + c0 + 2] * invN - m2 * m2 + EPS);
            float i3 = rsqrtf(g_stats[l][DD + c0 + 3] * invN - m3 * m3 + EPS);
            for (int n = blockIdx.x * 8 + rr; n < NN; n += NB * 8) {
                float4 v = *(const float4*)&g_out[(size_t)n * DD + c0];
                v.x = fast_tanh((v.x - m0) * i0);
                v.y = fast_tanh((v.y - m1) * i1);
                v.z = fast_tanh((v.z - m2) * i2);
                v.w = fast_tanh((v.w - m3) * i3);
                *(float4*)&xout[(size_t)n * DD + c0] = v;
            }
            if (blockIdx.x == NB - 1) {
                const float* wr = w_rel + l * DD * DD;
                for (int idx = tid; idx < RR * DD; idx += 256) {
                    int i = idx / DD, j = idx % DD;
                    float s = 0.f;
                    for (int k = 0; k < DD; k++)
                        s += rin[i * DD + k] * wr[k * DD + j];
                    rout[idx] = s;
                }
            }
        }
        gbar();
    }
}

// ---------------- launch ----------------------------------------------------
extern "C" void kernel_launch(void* const* d_in, const int* in_sizes, int n_in,
                              void* d_out, int out_size) {
    const float* x0       = (const float*)d_in[0];
    const float* r0       = (const float*)d_in[1];
    const float* w_in     = (const float*)d_in[2];
    const float* w_out    = (const float*)d_in[3];
    const float* w_loop   = (const float*)d_in[4];
    const float* w_rel    = (const float*)d_in[5];
    const float* loop_rel = (const float*)d_in[6];
    const float* bias     = (const float*)d_in[7];
    const int*   esrc     = (const int*)d_in[8];
    const int*   edst     = (const int*)d_in[9];
    const int*   etyp     = (const int*)d_in[10];

    float* out     = (float*)d_out;
    float* x_final = out;
    float* r_final = out + (size_t)NN * DD;

    int dev = 0;
    cudaGetDevice(&dev);
    int sms = 148;
    cudaDeviceGetAttribute(&sms, cudaDevAttrMultiProcessorCount, dev);
    int occ = 1;
    cudaOccupancyMaxActiveBlocksPerMultiprocessor(&occ, k_fused, 256, 0);
    if (occ < 1) occ = 1;
    int grid = sms * occ;

    k_fused<<<grid, 256>>>(x0, r0, w_in, w_out, w_loop, w_rel, loop_rel, bias,
                           esrc, edst, etyp, x_final, r_final);
}

// round 15
// speedup vs baseline: 6.0277x; 2.3669x over previous
#include <cuda_runtime.h>

#define NN 100000
#define EE 500000
#define DD 128
#define RR 10
#define EPS 1e-5f

#define BUCK_SH 8
#define NBUCK ((NN + 255) >> BUCK_SH)          // 391
#define NBLK  200
#define CHUNK ((EE + NBLK - 1) / NBLK)         // 2500
#define GEMM_TILES ((NN + 127) / 128)          // 782

typedef unsigned long long u64;
typedef unsigned int u32;

// ---------------- scratch (device globals; no allocation allowed) ----------
__device__ float g_agg_in [NN * DD];
__device__ float g_agg_out[NN * DD];
__device__ float g_out    [NN * DD];
__device__ float g_x      [NN * DD];
__device__ float g_stats  [2][2 * DD];
__device__ float g_r1     [RR * DD];

__device__ int   g_bhist [2][NBUCK][NBLK];
__device__ int   g_bpre  [2][NBUCK][NBLK];
__device__ int   g_btot  [2][NBUCK];
__device__ int   g_bstart[2][NBUCK + 1];
__device__ int   g_ebuf  [2][EE];    // (local<<21)|(type<<17)|nbr
__device__ int   g_off   [2][NN + 1];
__device__ float g_dinv  [2][NN];
__device__ int   g_nbr   [2][EE];    // (type<<17)|nbr

__device__ unsigned g_barc = 0;
__device__ unsigned g_barg = 0;

// ---------------- helpers ---------------------------------------------------
__device__ __forceinline__ float fast_tanh(float x) {
    float e = __expf(2.0f * x);
    return __fdividef(e - 1.0f, e + 1.0f);
}
__device__ __forceinline__ u32 f2tf(float f) {
    u32 u; asm("cvt.rna.tf32.f32 %0, %1;" : "=r"(u) : "f"(f)); return u;
}
__device__ __forceinline__ void mma_tf32(float* c, const u32* a, u32 b0, u32 b1) {
    asm volatile(
        "mma.sync.aligned.m16n8k8.row.col.f32.tf32.tf32.f32 "
        "{%0,%1,%2,%3},{%4,%5,%6,%7},{%8,%9},{%0,%1,%2,%3};"
        : "+f"(c[0]), "+f"(c[1]), "+f"(c[2]), "+f"(c[3])
        : "r"(a[0]), "r"(a[1]), "r"(a[2]), "r"(a[3]), "r"(b0), "r"(b1));
}

// grid-wide barrier: all blocks resident (grid sized by occupancy API)
__device__ __forceinline__ void gbar() {
    __syncthreads();
    if (threadIdx.x == 0) {
        __threadfence();
        unsigned gen = atomicAdd(&g_barg, 0u);
        if (atomicAdd(&g_barc, 1u) == gridDim.x - 1u) {
            atomicExch(&g_barc, 0u);
            __threadfence();
            atomicAdd(&g_barg, 1u);
        } else {
            while (atomicAdd(&g_barg, 0u) == gen) __nanosleep(200);
        }
        __threadfence();
    }
    __syncthreads();
}

// ---------------- the whole pipeline in one kernel --------------------------
__global__ __launch_bounds__(256, 2)
void k_fused(const float* __restrict__ x0, const float* __restrict__ r0,
             const float* __restrict__ w_in, const float* __restrict__ w_out,
             const float* __restrict__ w_loop, const float* __restrict__ w_rel,
             const float* __restrict__ loop_rel, const float* __restrict__ bias,
             const int* __restrict__ esrc, const int* __restrict__ edst,
             const int* __restrict__ etyp,
             float* __restrict__ x_final, float* __restrict__ r_final) {
    __shared__ __align__(16) unsigned char SU[49152];   // 48 KB union
    const int tid = threadIdx.x;
    const int NB = gridDim.x;

    // ===== Phase 0: bucket histograms + zero stats ==========================
    {
        int* bins = (int*)SU;
        if (blockIdx.x == 0)
            for (int i = tid; i < 4 * DD; i += 256) ((float*)g_stats)[i] = 0.f;
        for (int vb = blockIdx.x; vb < 2 * NBLK; vb += NB) {
            int dir = vb / NBLK, b = vb % NBLK;
            const int* __restrict__ key = dir ? edst : esrc;
            __syncthreads();
            for (int i = tid; i < NBUCK; i += 256) bins[i] = 0;
            __syncthreads();
            int beg = b * CHUNK, end = min(beg + CHUNK, EE);
            for (int e = beg + tid; e < end; e += 256)
                atomicAdd(&bins[key[e] >> BUCK_SH], 1);
            __syncthreads();
            for (int i = tid; i < NBUCK; i += 256)
                g_bhist[dir][i][b] = bins[i];
        }
    }
    gbar();

    // ===== Phase 1: per-bucket scan over blocks =============================
    {
        int* sm = (int*)SU;
        for (int vb = blockIdx.x; vb < 2 * NBUCK; vb += NB) {
            int dir = vb / NBUCK, bu = vb % NBUCK;
            __syncthreads();
            int v = (tid < NBLK) ? g_bhist[dir][bu][tid] : 0;
            sm[tid] = v;
            __syncthreads();
            for (int o = 1; o < 256; o <<= 1) {
                int u = (tid >= o) ? sm[tid - o] : 0;
                __syncthreads();
                sm[tid] += u;
                __syncthreads();
            }
            if (tid < NBLK) g_bpre[dir][bu][tid] = sm[tid] - v;
            if (tid == 255) g_btot[dir][bu] = sm[255];
        }
    }
    gbar();

    // ===== Phase 2: top scan over buckets (block 0) =========================
    if (blockIdx.x == 0) {
        int* sm = (int*)SU;
        for (int dir = 0; dir < 2; dir++) {
            int e0 = 2 * tid, e1 = 2 * tid + 1;
            int v0 = (e0 < NBUCK) ? g_btot[dir][e0] : 0;
            int v1 = (e1 < NBUCK) ? g_btot[dir][e1] : 0;
            int p = v0 + v1;
            __syncthreads();
            sm[tid] = p;
            __syncthreads();
            for (int o = 1; o < 256; o <<= 1) {
                int u = (tid >= o) ? sm[tid - o] : 0;
                __syncthreads();
                sm[tid] += u;
                __syncthreads();
            }
            int excl = sm[tid] - p;
            if (e0 < NBUCK) g_bstart[dir][e0] = excl;
            if (e1 < NBUCK) g_bstart[dir][e1] = excl + v0;
        }
        if (tid == 0) {
            g_bstart[0][NBUCK] = EE; g_bstart[1][NBUCK] = EE;
            g_off[0][NN] = EE; g_off[1][NN] = EE;
        }
    }
    gbar();

    // ===== Phase 3: scatter into buckets ====================================
    {
        int* cur = (int*)SU;
        for (int vb = blockIdx.x; vb < 2 * NBLK; vb += NB) {
            int dir = vb / NBLK, b = vb % NBLK;
            const int* __restrict__ key = dir ? edst : esrc;
            const int* __restrict__ oth = dir ? esrc : edst;
            __syncthreads();
            for (int i = tid; i < NBUCK; i += 256)
                cur[i] = g_bstart[dir][i] + g_bpre[dir][i][b];
            __syncthreads();
            int beg = b * CHUNK, end = min(beg + CHUNK, EE);
            for (int e = beg + tid; e < end; e += 256) {
                int k = key[e];
                int pos = atomicAdd(&cur[k >> BUCK_SH], 1);
                g_ebuf[dir][pos] = ((k & 255) << 21) | (etyp[e] << 17) | oth[e];
            }
        }
    }
    gbar();

    // ===== Phase 4: finalize CSR per bucket =================================
    {
        int* cnt = (int*)SU;
        int* pre = cnt + 256;
        for (int vb = blockIdx.x; vb < 2 * NBUCK; vb += NB) {
            int dir = vb / NBUCK, bu = vb % NBUCK;
            int beg = g_bstart[dir][bu], end = g_bstart[dir][bu + 1];
            __syncthreads();
            cnt[tid] = 0;
            __syncthreads();
            for (int p = beg + tid; p < end; p += 256)
                atomicAdd(&cnt[g_ebuf[dir][p] >> 21], 1);
            __syncthreads();
            int v = cnt[tid];
            pre[tid] = v;
            __syncthreads();
            for (int o = 1; o < 256; o <<= 1) {
                int u = (tid >= o) ? pre[tid - o] : 0;
                __syncthreads();
                pre[tid] += u;
                __syncthreads();
            }
            int excl = pre[tid] - v;
            int node = (bu << BUCK_SH) + tid;
            if (node < NN) {
                g_off[dir][node] = beg + excl;
                g_dinv[dir][node] = (v > 0) ? rsqrtf((float)v) : 0.0f;
            }
            __syncthreads();
            cnt[tid] = excl;
            __syncthreads();
            for (int p = beg + tid; p < end; p += 256) {
                int e = g_ebuf[dir][p];
                int pos = beg + atomicAdd(&cnt[e >> 21], 1);
                g_nbr[dir][pos] = e & 0x1FFFFF;
            }
        }
    }
    gbar();

    // ===== Layers ===========================================================
    for (int l = 0; l < 2; l++) {
        const float* xin = l ? g_x : x0;
        const float* rin = l ? g_r1 : r0;
        const float* B0 = w_in  + l * DD * DD;
        const float* B1 = w_out + l * DD * DD;
        const float* B2w = w_loop + l * DD * DD;
        const float* lr = loop_rel + l * DD;
        const float* bi = bias + l * DD;
        float* xout = l ? x_final : g_x;
        float* rout = l ? r_final : g_r1;

        // ---- aggregation (warp per (node,dir)) ----
        {
            float* rs = (float*)SU;
            for (int i = tid; i < RR * DD; i += 256) rs[i] = rin[i];
            __syncthreads();
            int wid = tid >> 5, lane = tid & 31;
            const float4* x4 = (const float4*)xin;
            for (int pr = blockIdx.x * 8 + wid; pr < 2 * NN; pr += NB * 8) {
                int dir = pr >= NN;
                int n = pr - (dir ? NN : 0);
                const int* __restrict__ off = g_off[dir];
                const int* __restrict__ nbr = g_nbr[dir];
                const float* __restrict__ dinv = g_dinv[dir];
                float* __restrict__ agg = dir ? g_agg_out : g_agg_in;
                int beg = off[n], end = off[n + 1];
                float4 acc = make_float4(0.f, 0.f, 0.f, 0.f);
                int p = beg;
                for (; p + 4 <= end; p += 4) {
                    int pk0 = nbr[p], pk1 = nbr[p + 1];
                    int pk2v = nbr[p + 2], pk3 = nbr[p + 3];
                    int m0 = pk0 & 0x1FFFF, m1 = pk1 & 0x1FFFF;
                    int m2 = pk2v & 0x1FFFF, m3 = pk3 & 0x1FFFF;
                    float dv0 = dinv[m0], dv1 = dinv[m1];
                    float dv2 = dinv[m2], dv3 = dinv[m3];
                    float4 xv0 = x4[m0 * 32 + lane];
                    float4 xv1 = x4[m1 * 32 + lane];
                    float4 xv2 = x4[m2 * 32 + lane];
                    float4 xv3 = x4[m3 * 32 + lane];
                    float4 rv0 = *(const float4*)&rs[(pk0 >> 17) * DD + lane * 4];
                    float4 rv1 = *(const float4*)&rs[(pk1 >> 17) * DD + lane * 4];
                    float4 rv2 = *(const float4*)&rs[(pk2v >> 17) * DD + lane * 4];
                    float4 rv3 = *(const float4*)&rs[(pk3 >> 17) * DD + lane * 4];
                    acc.x += dv0 * xv0.x * rv0.x + dv1 * xv1.x * rv1.x
                           + dv2 * xv2.x * rv2.x + dv3 * xv3.x * rv3.x;
                    acc.y += dv0 * xv0.y * rv0.y + dv1 * xv1.y * rv1.y
                           + dv2 * xv2.y * rv2.y + dv3 * xv3.y * rv3.y;
                    acc.z += dv0 * xv0.z * rv0.z + dv1 * xv1.z * rv1.z
                           + dv2 * xv2.z * rv2.z + dv3 * xv3.z * rv3.z;
                    acc.w += dv0 * xv0.w * rv0.w + dv1 * xv1.w * rv1.w
                           + dv2 * xv2.w * rv2.w + dv3 * xv3.w * rv3.w;
                }
                for (; p < end; p++) {
                    int pk = nbr[p];
                    int m = pk & 0x1FFFF;
                    float dv = dinv[m];
                    float4 xv = x4[m * 32 + lane];
                    float4 rv = *(const float4*)&rs[(pk >> 17) * DD + lane * 4];
                    acc.x += dv * xv.x * rv.x;
                    acc.y += dv * xv.y * rv.y;
                    acc.z += dv * xv.z * rv.z;
                    acc.w += dv * xv.w * rv.w;
                }
                float own = dinv[n];
                acc.x *= own; acc.y *= own; acc.z *= own; acc.w *= own;
                *(float4*)&agg[(size_t)n * DD + lane * 4] = acc;
            }
        }
        gbar();

        // ---- GEMM via tf32 mma.sync + bias + BN partial stats ----
        {
            u32 (*A_s)[36]  = (u32(*)[36])SU;                    // 18432 B
            u32 (*B_s)[136] = (u32(*)[136])(SU + 128 * 36 * 4);  // 17408 B
            const int lane = tid & 31, wid = tid >> 5;
            const int wr = wid >> 1, wc = wid & 1;   // warp 32x64 tile
            const int qr = lane >> 2, qc = lane & 3;

            for (int tile = blockIdx.x; tile < GEMM_TILES; tile += NB) {
                const int rowBase = tile * 128;
                float C[2][8][4];
#pragma unroll
                for (int m = 0; m < 2; m++)
#pragma unroll
                    for (int n = 0; n < 8; n++)
#pragma unroll
                        for (int j = 0; j < 4; j++) C[m][n][j] = 0.f;

                for (int c = 0; c < 3; c++) {
                    const float* A = (c == 0) ? g_agg_in : (c == 1) ? g_agg_out : xin;
                    const float* B = (c == 0) ? B0 : (c == 1) ? B1 : B2w;
                    for (int ks = 0; ks < 4; ks++) {
                        __syncthreads();
                        {   // stage A: 128 rows x 32 k, cvt to tf32
                            int k4 = tid & 7;
                            int r0i = tid >> 3;
#pragma unroll
                            for (int rr = 0; rr < 4; rr++) {
                                int row = r0i + rr * 32;
                                int grow = rowBase + row;
                                float4 v = make_float4(0.f, 0.f, 0.f, 0.f);
                                if (grow < NN)
                                    v = *(const float4*)&A[(size_t)grow * DD + ks * 32 + k4 * 4];
                                uint4 w = make_uint4(f2tf(v.x), f2tf(v.y), f2tf(v.z), f2tf(v.w));
                                *(uint4*)&A_s[row][k4 * 4] = w;
                            }
                        }
                        {   // stage B: 32 k x 128 col, cvt to tf32 (+loop scale)
                            int c4 = tid & 31;
                            int k0 = tid >> 5;
#pragma unroll
                            for (int p = 0; p < 4; p++) {
                                int kk = k0 + p * 8;
                                int gk = ks * 32 + kk;
                                float4 v = *(const float4*)&B[gk * DD + c4 * 4];
                                if (c == 2) {
                                    float sc = lr[gk];
                                    v.x *= sc; v.y *= sc; v.z *= sc; v.w *= sc;
                                }
                                uint4 w = make_uint4(f2tf(v.x), f2tf(v.y), f2tf(v.z), f2tf(v.w));
                                *(uint4*)&B_s[kk][c4 * 4] = w;
                            }
                        }
                        __syncthreads();
#pragma unroll
                        for (int kk = 0; kk < 32; kk += 8) {
                            u32 a[2][4];
#pragma unroll
                            for (int m = 0; m < 2; m++) {
                                int r = wr * 32 + m * 16 + qr;
                                a[m][0] = A_s[r][kk + qc];
                                a[m][1] = A_s[r + 8][kk + qc];
                                a[m][2] = A_s[r][kk + qc + 4];
                                a[m][3] = A_s[r + 8][kk + qc + 4];
                            }
#pragma unroll
                            for (int n = 0; n < 8; n++) {
                                int cl = wc * 64 + n * 8 + qr;
                                u32 b0 = B_s[kk + qc][cl];
                                u32 b1 = B_s[kk + qc + 4][cl];
                                mma_tf32(C[0][n], a[0], b0, b1);
                                mma_tf32(C[1][n], a[1], b0, b1);
                            }
                        }
                    }
                }

                // epilogue: /3 + bias + store + BN partial stats
                const float third = 1.0f / 3.0f;
                float scol[16], qcol[16];
#pragma unroll
                for (int j = 0; j < 16; j++) { scol[j] = 0.f; qcol[j] = 0.f; }
#pragma unroll
                for (int m = 0; m < 2; m++) {
#pragma unroll
                    for (int n = 0; n < 8; n++) {
                        int col = wc * 64 + n * 8 + qc * 2;
                        float b0v = bi[col], b1v = bi[col + 1];
                        int ra = rowBase + wr * 32 + m * 16 + qr;
                        int rb = ra + 8;
                        float lo0 = C[m][n][0] * third + b0v;
                        float hi0 = C[m][n][1] * third + b1v;
                        float lo1 = C[m][n][2] * third + b0v;
                        float hi1 = C[m][n][3] * third + b1v;
                        if (ra < NN) {
                            *(float2*)&g_out[(size_t)ra * DD + col] = make_float2(lo0, hi0);
                            scol[n * 2]     += lo0; qcol[n * 2]     += lo0 * lo0;
                            scol[n * 2 + 1] += hi0; qcol[n * 2 + 1] += hi0 * hi0;
                        }
                        if (rb < NN) {
                            *(float2*)&g_out[(size_t)rb * DD + col] = make_float2(lo1, hi1);
                            scol[n * 2]     += lo1; qcol[n * 2]     += lo1 * lo1;
                            scol[n * 2 + 1] += hi1; qcol[n * 2 + 1] += hi1 * hi1;
                        }
                    }
                }

                __syncthreads();
                float* ssum = (float*)SU;
                float* ssq  = ssum + DD;
                if (tid < DD) { ssum[tid] = 0.f; ssq[tid] = 0.f; }
                __syncthreads();
#pragma unroll
                for (int n = 0; n < 8; n++) {
#pragma unroll
                    for (int b = 0; b < 2; b++) {
                        int col = wc * 64 + n * 8 + qc * 2 + b;
                        atomicAdd(&ssum[col], scol[n * 2 + b]);
                        atomicAdd(&ssq[col], qcol[n * 2 + b]);
                    }
                }
                __syncthreads();
                if (tid < DD) {
                    atomicAdd(&g_stats[l][tid], ssum[tid]);
                    atomicAdd(&g_stats[l][DD + tid], ssq[tid]);
                }
                __syncthreads();
            }
        }
        gbar();

        // ---- BN normalize + tanh, and relation transform ----
        {
            int cg = tid & 31;
            int rr = tid >> 5;
            int c0 = cg * 4;
            const float invN = 1.0f / NN;
            float m0 = g_stats[l][c0] * invN,     m1 = g_stats[l][c0 + 1] * invN;
            float m2 = g_stats[l][c0 + 2] * invN, m3 = g_stats[l][c0 + 3] * invN;
            float i0 = rsqrtf(g_stats[l][DD + c0] * invN - m0 * m0 + EPS);
            float i1 = rsqrtf(g_stats[l][DD + c0 + 1] * invN - m1 * m1 + EPS);
            float i2 = rsqrtf(g_stats[l][DD + c0 + 2] * invN - m2 * m2 + EPS);
            float i3 = rsqrtf(g_stats[l][DD + c0 + 3] * invN - m3 * m3 + EPS);
            for (int n = blockIdx.x * 8 + rr; n < NN; n += NB * 8) {
                float4 v = *(const float4*)&g_out[(size_t)n * DD + c0];
                v.x = fast_tanh((v.x - m0) * i0);
                v.y = fast_tanh((v.y - m1) * i1);
                v.z = fast_tanh((v.z - m2) * i2);
                v.w = fast_tanh((v.w - m3) * i3);
                *(float4*)&xout[(size_t)n * DD + c0] = v;
            }
            if (blockIdx.x == NB - 1) {
                const float* wr2 = w_rel + l * DD * DD;
                for (int idx = tid; idx < RR * DD; idx += 256) {
                    int i = idx / DD, j = idx % DD;
                    float s = 0.f;
                    for (int k = 0; k < DD; k++)
                        s += rin[i * DD + k] * wr2[k * DD + j];
                    rout[idx] = s;
                }
            }
        }
        gbar();
    }
}

// ---------------- launch ----------------------------------------------------
extern "C" void kernel_launch(void* const* d_in, const int* in_sizes, int n_in,
                              void* d_out, int out_size) {
    const float* x0       = (const float*)d_in[0];
    const float* r0       = (const float*)d_in[1];
    const float* w_in     = (const float*)d_in[2];
    const float* w_out    = (const float*)d_in[3];
    const float* w_loop   = (const float*)d_in[4];
    const float* w_rel    = (const float*)d_in[5];
    const float* loop_rel = (const float*)d_in[6];
    const float* bias     = (const float*)d_in[7];
    const int*   esrc     = (const int*)d_in[8];
    const int*   edst     = (const int*)d_in[9];
    const int*   etyp     = (const int*)d_in[10];

    float* out     = (float*)d_out;
    float* x_final = out;
    float* r_final = out + (size_t)NN * DD;

    int dev = 0;
    cudaGetDevice(&dev);
    int sms = 148;
    cudaDeviceGetAttribute(&sms, cudaDevAttrMultiProcessorCount, dev);
    int occ = 1;
    cudaOccupancyMaxActiveBlocksPerMultiprocessor(&occ, k_fused, 256, 0);
    if (occ < 1) occ = 1;
    int grid = sms * occ;

    k_fused<<<grid, 256>>>(x0, r0, w_in, w_out, w_loop, w_rel, loop_rel, bias,
                           esrc, edst, etyp, x_final, r_final);
}